// round 16
// baseline (speedup 1.0000x reference)
#include <cuda_runtime.h>

// FFM pairwise interactions:
//   inputs: (B=4096, 400, 64) fp32, v[b, j, i, e]
//   output: (B, 1, 190, 64) fp32, out[b,0,p,:] = v[b,jj,ii,:] * v[b,ii,jj,:]
//
// HBM streaming at the 597 MB floor (~86% DRAM ceiling confirmed R1-R12).
// R12: in-row ILP=2 — each thread handles quads q and q+8 of the SAME pair
// row, so its two a-loads / two c-loads / two stores pair within one 256-B
// row (same DRAM page, same L2 line pair). Fine granularity of the
// wall-clock-best R1/R10 mapping, half the decode work, 4 LDG.128 in flight.

constexpr int N_FIELDS = 20;
constexpr int NPAIRS   = 190;
constexpr int QUADS    = 16;                           // float4 per 64-elem row
constexpr int ROW_F4   = N_FIELDS * N_FIELDS * QUADS;  // 6400 float4 per batch
constexpr int TOTAL_T  = 4096 * NPAIRS * 8;            // threads: 2 quads each
constexpr int THREADS  = 256;
constexpr int BLOCKS   = TOTAL_T / THREADS;            // 24300 exact

// Per-pair float4 offsets: offA[p] = (j*20+i)*16, offC[p] = (i*20+j)*16
struct PairTab { unsigned short offA[NPAIRS]; unsigned short offC[NPAIRS]; };
constexpr PairTab make_tab() {
    PairTab t{};
    int p = 0;
    for (int i = 0; i < N_FIELDS; ++i)
        for (int j = i + 1; j < N_FIELDS; ++j, ++p) {
            t.offA[p] = (unsigned short)((j * N_FIELDS + i) * QUADS);
            t.offC[p] = (unsigned short)((i * N_FIELDS + j) * QUADS);
        }
    return t;
}
__constant__ PairTab TAB = make_tab();

__global__ void __launch_bounds__(THREADS)
ffm_pair_kernel(const float4* __restrict__ in, float4* __restrict__ out)
{
    int t  = blockIdx.x * THREADS + threadIdx.x;   // < TOTAL_T (exact grid)

    int q  = t & 7;              // first quad (second is q+8, same row)
    int bp = t >> 3;             // b * NPAIRS + p
    int p  = bp % NPAIRS;        // magic-mul
    int b  = bp / NPAIRS;

    const float4* base = in + (long)b * ROW_F4 + q;
    const float4* pa = base + TAB.offA[p];   // v[b, j, i, :]
    const float4* pc = base + TAB.offC[p];   // v[b, i, j, :]

    // 4 independent streaming loads; both halves of each row pair in the
    // same DRAM page.
    float4 a0 = __ldcs(pa);
    float4 a1 = __ldcs(pa + 8);
    float4 c0 = __ldcs(pc);
    float4 c1 = __ldcs(pc + 8);

    float4 r0, r1;
    r0.x = a0.x * c0.x; r0.y = a0.y * c0.y; r0.z = a0.z * c0.z; r0.w = a0.w * c0.w;
    r1.x = a1.x * c1.x; r1.y = a1.y * c1.y; r1.z = a1.z * c1.z; r1.w = a1.w * c1.w;

    float4* po = out + (long)bp * QUADS + q;
    __stcs(po,     r0);
    __stcs(po + 8, r1);
}

extern "C" void kernel_launch(void* const* d_in, const int* in_sizes, int n_in,
                              void* d_out, int out_size)
{
    const float4* in  = (const float4*)d_in[0];
    float4*       out = (float4*)d_out;
    ffm_pair_kernel<<<BLOCKS, THREADS>>>(in, out);
}